// round 10
// baseline (speedup 1.0000x reference)
#include <cuda_runtime.h>
#include <math.h>
#include <stdint.h>

#define NEXP 64
#define KSEL 8
#define DDIM 1024
#define MTILE 64
#define KC 32
#define NCHUNK (DDIM / KC)   // 32
#define MAXBLK 1024

typedef unsigned long long ull;

__device__ float g_part[MAXBLK * NEXP];
// w duplicated into packed f32x2 pairs, transposed: Bdup[k][e] = (w[e][k], w[e][k])
__device__ __align__(16) float2 Bdup[DDIM * NEXP];

// packed dual-FMA: d.lo = a.lo*b.lo + d.lo ; d.hi = a.hi*b.hi + d.hi
#define FMA2(acc, a, b) \
    asm("fma.rn.f32x2 %0, %1, %2, %0;" : "+l"(acc) : "l"(a), "l"(b))

// ---- prep: duplicate + transpose w ----
__global__ void bprep_kernel(const float* __restrict__ w)
{
    int idx = blockIdx.x * 256 + threadIdx.x;   // 0..65535
    int e = idx >> 10;                          // expert
    int k = idx & 1023;
    float v = w[idx];                           // w[e][k], coalesced
    Bdup[k * NEXP + e] = make_float2(v, v);
}

__global__ void __launch_bounds__(256, 2) gate_kernel(
    const float* __restrict__ x,
    const float* __restrict__ nw, const float* __restrict__ noise,
    float* __restrict__ out_w, float* __restrict__ out_ids)
{
    // Union: As[2][32][66] (4224 f) <-> epilogue canvas U[64][65] (4160 f)
    __shared__ __align__(16) float SM[2 * KC * 66];
    __shared__ float nw_s[NEXP];
    __shared__ float wsum[2][NEXP];

    const int tid  = threadIdx.x;
    const int wid  = tid >> 5;          // 0..7
    const int lane = tid & 31;
    const int rp   = lane & 15;         // row-pair 0..15
    const int eh   = lane >> 4;         // expert-half of this warp's 8
    const int ebase = wid * 8 + eh * 4; // 4 experts per thread
    const int base = blockIdx.x * MTILE;

    if (tid < NEXP) nw_s[tid] = nw[tid];

    // staging map: thread stages row sr, k-segment sseg (8 floats)
    const int sr = tid >> 2;            // 0..63
    const int sseg = tid & 3;           // 0..3
    const float* xrow = x + (size_t)(base + sr) * DDIM + sseg * 8;

#define STS8(buf, v0, v1) do {                                                 \
    float _t[8] = {(v0).x, (v0).y, (v0).z, (v0).w,                             \
                   (v1).x, (v1).y, (v1).z, (v1).w};                            \
    _Pragma("unroll")                                                          \
    for (int _j = 0; _j < 8; _j++)                                             \
        SM[(buf) * (KC * 66) + (sseg * 8 + _j) * 66 + sr] = _t[_j];            \
} while (0)

    ull acc[2][4];
#pragma unroll
    for (int p = 0; p < 2; p++)
#pragma unroll
        for (int e = 0; e < 4; e++) acc[p][e] = 0ull;

    // prologue: stage chunk 0
    {
        float4 v0 = *(const float4*)(xrow);
        float4 v1 = *(const float4*)(xrow + 4);
        STS8(0, v0, v1);
    }
    __syncthreads();

#pragma unroll 1
    for (int ch = 0; ch < NCHUNK; ch++) {
        float4 v0, v1;
        if (ch + 1 < NCHUNK) {
            v0 = *(const float4*)(xrow + (ch + 1) * KC);
            v1 = *(const float4*)(xrow + (ch + 1) * KC + 4);
        }
        const float* As = SM + (ch & 1) * (KC * 66);
        const float2* bk = Bdup + (size_t)ch * KC * NEXP + ebase;
#pragma unroll
        for (int k = 0; k < KC; k++) {
            ull a0 = *(const ull*)(As + k * 66 + rp * 2);
            ull a1 = *(const ull*)(As + k * 66 + rp * 2 + 32);
            ulonglong2 b01 = *(const ulonglong2*)(bk + k * NEXP);
            ulonglong2 b23 = *(const ulonglong2*)(bk + k * NEXP + 2);
            FMA2(acc[0][0], a0, b01.x);
            FMA2(acc[0][1], a0, b01.y);
            FMA2(acc[0][2], a0, b23.x);
            FMA2(acc[0][3], a0, b23.y);
            FMA2(acc[1][0], a1, b01.x);
            FMA2(acc[1][1], a1, b01.y);
            FMA2(acc[1][2], a1, b23.x);
            FMA2(acc[1][3], a1, b23.y);
        }
        if (ch + 1 < NCHUNK) STS8((ch + 1) & 1, v0, v1);
        __syncthreads();
    }

    // ---- unpack accumulators into canvas U[64][65] (As now dead) ----
    {
        float* U = SM;
#pragma unroll
        for (int p = 0; p < 2; p++) {
            int r = rp * 2 + p * 32;
#pragma unroll
            for (int e = 0; e < 4; e++) {
                uint2 u = *(uint2*)&acc[p][e];
                U[r * 65 + ebase + e]       = __uint_as_float(u.x);
                U[(r + 1) * 65 + ebase + e] = __uint_as_float(u.y);
            }
        }
    }
    __syncthreads();

    // ---- epilogue: threads 0..63 own one row each (2 warps) ----
    if (tid < MTILE) {
        const float* U = SM;
        const int r = tid;
        const int w2 = tid >> 5;   // 0..1
        float L[64];
#pragma unroll
        for (int e = 0; e < 64; e++) L[e] = U[r * 65 + e];

        float m = -INFINITY;
#pragma unroll
        for (int e = 0; e < 64; e++) m = fmaxf(m, L[e]);
        float s = 0.f;
#pragma unroll
        for (int e = 0; e < 64; e++) s += __expf(L[e] - m);
        float sinv = 1.f / s;

        // per-expert column sums over this warp's 32 rows (deterministic)
#pragma unroll
        for (int e = 0; e < 64; e++) {
            float v = __expf(L[e] - m) * sinv;
            v += __shfl_xor_sync(0xffffffffu, v, 16);
            v += __shfl_xor_sync(0xffffffffu, v, 8);
            v += __shfl_xor_sync(0xffffffffu, v, 4);
            v += __shfl_xor_sync(0xffffffffu, v, 2);
            v += __shfl_xor_sync(0xffffffffu, v, 1);
            if ((e & 31) == lane) wsum[w2][e] = v;
        }

        // noisy logits
        const float4* np = (const float4*)(noise + (size_t)(base + r) * NEXP);
#pragma unroll
        for (int q = 0; q < 16; q++) {
            float4 nv = np[q];
            L[q * 4 + 0] = fmaf(nv.x, nw_s[q * 4 + 0], L[q * 4 + 0]);
            L[q * 4 + 1] = fmaf(nv.y, nw_s[q * 4 + 1], L[q * 4 + 1]);
            L[q * 4 + 2] = fmaf(nv.z, nw_s[q * 4 + 2], L[q * 4 + 2]);
            L[q * 4 + 3] = fmaf(nv.w, nw_s[q * 4 + 3], L[q * 4 + 3]);
        }

        // top-8 (strict >, lowest index wins ties)
        float best[KSEL];
        int bid[KSEL];
        unsigned long long used = 0ull;
#pragma unroll
        for (int k = 0; k < KSEL; k++) {
            float mv = -INFINITY;
            int mi = 0;
#pragma unroll
            for (int e = 0; e < 64; e++) {
                bool ok = !((used >> e) & 1ull);
                if (ok && L[e] > mv) { mv = L[e]; mi = e; }
            }
            used |= 1ull << mi;
            best[k] = mv;
            bid[k] = mi;
        }
        float m0 = best[0];
        float ss = 0.f;
#pragma unroll
        for (int k = 0; k < KSEL; k++) ss += __expf(best[k] - m0);
        float inv = 1.f / ss;

        float4 z = {0.f, 0.f, 0.f, 0.f};
        float4* ow = (float4*)(out_w + (size_t)(base + r) * NEXP);
#pragma unroll
        for (int q = 0; q < 16; q++) ow[q] = z;
#pragma unroll
        for (int k = 0; k < KSEL; k++) {
            out_w[(size_t)(base + r) * NEXP + bid[k]] = __expf(best[k] - m0) * inv;
            out_ids[(size_t)(base + r) * KSEL + k] = (float)bid[k];
        }
    }
    __syncthreads();
    if (tid < NEXP)
        g_part[blockIdx.x * NEXP + tid] = wsum[0][tid] + wsum[1][tid];
}

__global__ void __launch_bounds__(1024) loss_kernel(
    int nBlocks, int N, float* __restrict__ out_loss)
{
    __shared__ double red[1024];
    const int t = threadIdx.x;
    const int e = t & 63, g = t >> 6;  // 16 partials per expert
    double s = 0.0;
    for (int b = g; b < nBlocks; b += 16) s += (double)g_part[b * NEXP + e];
    red[t] = s;
    __syncthreads();
    for (int off = 512; off >= 64; off >>= 1) {
        if (t < off) red[t] += red[t + off];
        __syncthreads();
    }
    if (t < 64) {
        double d = red[t] / (double)N - 1.0 / 64.0;
        red[t] = d * d;
    }
    __syncthreads();
    for (int off = 32; off >= 1; off >>= 1) {
        if (t < off) red[t] += red[t + off];
        __syncthreads();
    }
    if (t == 0) *out_loss = (float)(red[0] / 64.0 * 0.01);
}

extern "C" void kernel_launch(void* const* d_in, const int* in_sizes, int n_in,
                              void* d_out, int out_size)
{
    const float* x     = (const float*)d_in[0];  // [N, 1024]
    const float* w     = (const float*)d_in[1];  // [64, 1024]
    const float* nw    = (const float*)d_in[2];  // [64]
    const float* noise = (const float*)d_in[3];  // [N, 64]

    int N = in_sizes[3] / NEXP;
    int nBlocks = N / MTILE;

    float* out      = (float*)d_out;
    float* out_w    = out;                                        // [N, 64]
    float* out_ids  = out + (size_t)N * NEXP;                     // [N, 8]
    float* out_loss = out + (size_t)N * NEXP + (size_t)N * KSEL;  // [1]

    bprep_kernel<<<256, 256>>>(w);
    gate_kernel<<<nBlocks, 256>>>(x, nw, noise, out_w, out_ids);
    loss_kernel<<<1, 1024>>>(nBlocks, N, out_loss);
}

// round 11
// speedup vs baseline: 1.2267x; 1.2267x over previous
#include <cuda_runtime.h>
#include <cuda_fp16.h>
#include <math.h>
#include <stdint.h>

#define NEXP 64
#define KSEL 8
#define DDIM 1024
#define NCHUNK 32
#define S11 2048.0f
#define I11 4.8828125e-4f
#define STEP_STRIDE 1024
#define NSLOT 1024            // g_part granularity: 32 rows/slot
#define NA 640                // type-A CTAs (32 rows each) = 20480 rows
#define ROWS_A (NA * 32)

__device__ float g_part[NSLOT * NEXP];
__device__ uint32_t Bfrag[NCHUNK * 2 * 2 * 8 * 64];

__device__ __forceinline__ uint32_t h2u(half2 h) {
    return *reinterpret_cast<uint32_t*>(&h);
}
__device__ __forceinline__ void split2(float2 v, uint32_t& h, uint32_t& l) {
    half2 hh = __float22half2_rn(v);
    float2 hb = __half22float2(hh);
    half2 ll = __float22half2_rn(
        make_float2((v.x - hb.x) * S11, (v.y - hb.y) * S11));
    h = h2u(hh);
    l = h2u(ll);
}

#define MMA_F16_ACC(cc, a, b0, b1)                                             \
    asm volatile(                                                              \
        "mma.sync.aligned.m16n8k16.row.col.f32.f16.f16.f32 "                   \
        "{%0,%1,%2,%3},{%4,%5,%6,%7},{%8,%9},{%0,%1,%2,%3};"                   \
        : "+f"((cc)[0]), "+f"((cc)[1]), "+f"((cc)[2]), "+f"((cc)[3])           \
        : "r"((a)[0]), "r"((a)[1]), "r"((a)[2]), "r"((a)[3]),                  \
          "r"(b0), "r"(b1))
#define MMA_F16_NEW(dd, a, b0, b1)                                             \
    asm volatile(                                                              \
        "mma.sync.aligned.m16n8k16.row.col.f32.f16.f16.f32 "                   \
        "{%0,%1,%2,%3},{%4,%5,%6,%7},{%8,%9},{%10,%11,%12,%13};"               \
        : "=f"((dd)[0]), "=f"((dd)[1]), "=f"((dd)[2]), "=f"((dd)[3])           \
        : "r"((a)[0]), "r"((a)[1]), "r"((a)[2]), "r"((a)[3]),                  \
          "r"(b0), "r"(b1),                                                    \
          "f"(0.0f), "f"(0.0f), "f"(0.0f), "f"(0.0f))

__global__ void wsplit_kernel(const float* __restrict__ w)
{
    int idx = blockIdx.x * 256 + threadIdx.x;
    int n = idx >> 9;
    int kp = idx & 511;
    float2 v = *(const float2*)(w + (size_t)n * DDIM + kp * 2);
    uint32_t h, l;
    split2(v, h, l);
    int k = kp * 2;
    int ch = k >> 5, win = k & 31;
    int s = win >> 4, kk = win & 15;
    int sl = kk >> 3, q = (kk & 7) >> 1;
    int tile = n >> 3, lane = (n & 7) * 4 + q;
    uint32_t base = (uint32_t)(ch * 2 + s) * STEP_STRIDE + tile * 64 + lane * 2 + sl;
    Bfrag[base]       = h;
    Bfrag[base + 512] = l;
}

// Row-wise epilogue: softmax stats -> shfl column-reduce -> noise -> top8 -> out
__device__ __forceinline__ void row_epilogue(
    const float* U, int r, int gbase, int lane, float* wsum_row,
    const float* nw_s, const float* __restrict__ noise,
    float* __restrict__ out_w, float* __restrict__ out_ids)
{
    float L[64];
#pragma unroll
    for (int e = 0; e < 64; e++) L[e] = U[r * 65 + e];
    float m = -INFINITY;
#pragma unroll
    for (int e = 0; e < 64; e++) m = fmaxf(m, L[e]);
    float s = 0.f;
#pragma unroll
    for (int e = 0; e < 64; e++) s += __expf(L[e] - m);
    float sinv = 1.f / s;
#pragma unroll
    for (int e = 0; e < 64; e++) {
        float v = __expf(L[e] - m) * sinv;
        v += __shfl_xor_sync(0xffffffffu, v, 16);
        v += __shfl_xor_sync(0xffffffffu, v, 8);
        v += __shfl_xor_sync(0xffffffffu, v, 4);
        v += __shfl_xor_sync(0xffffffffu, v, 2);
        v += __shfl_xor_sync(0xffffffffu, v, 1);
        if ((e & 31) == lane) wsum_row[e] = v;
    }
    const float4* np = (const float4*)(noise + (size_t)(gbase + r) * NEXP);
#pragma unroll
    for (int q = 0; q < 16; q++) {
        float4 nv = np[q];
        L[q * 4 + 0] = fmaf(nv.x, nw_s[q * 4 + 0], L[q * 4 + 0]);
        L[q * 4 + 1] = fmaf(nv.y, nw_s[q * 4 + 1], L[q * 4 + 1]);
        L[q * 4 + 2] = fmaf(nv.z, nw_s[q * 4 + 2], L[q * 4 + 2]);
        L[q * 4 + 3] = fmaf(nv.w, nw_s[q * 4 + 3], L[q * 4 + 3]);
    }
    float best[KSEL];
    int bid[KSEL];
    unsigned long long used = 0ull;
#pragma unroll
    for (int k = 0; k < KSEL; k++) {
        float mv = -INFINITY;
        int mi = 0;
#pragma unroll
        for (int e = 0; e < 64; e++) {
            bool ok = !((used >> e) & 1ull);
            if (ok && L[e] > mv) { mv = L[e]; mi = e; }
        }
        used |= 1ull << mi;
        best[k] = mv;
        bid[k] = mi;
    }
    float m0 = best[0];
    float ss = 0.f;
#pragma unroll
    for (int k = 0; k < KSEL; k++) ss += __expf(best[k] - m0);
    float inv = 1.f / ss;
    float4 z = {0.f, 0.f, 0.f, 0.f};
    float4* ow = (float4*)(out_w + (size_t)(gbase + r) * NEXP);
#pragma unroll
    for (int q = 0; q < 16; q++) ow[q] = z;
#pragma unroll
    for (int k = 0; k < KSEL; k++) {
        out_w[(size_t)(gbase + r) * NEXP + bid[k]] = __expf(best[k] - m0) * inv;
        out_ids[(size_t)(gbase + r) * KSEL + k] = (float)bid[k];
    }
}

__global__ void __launch_bounds__(128, 5) gate_kernel(
    const float* __restrict__ x, const float* __restrict__ w,
    const float* __restrict__ nw, const float* __restrict__ noise,
    float* __restrict__ out_w, float* __restrict__ out_ids)
{
    // Union: B-GEMM tiles As[32][68]+Bs[32][68] = 4352 f; canvases fit inside
    __shared__ __align__(16) float SM[4352];
    __shared__ float nw_s[NEXP];
    __shared__ float wsum[2][NEXP];

    const int tid  = threadIdx.x;
    const int wid  = tid >> 5;
    const int lane = tid & 31;
    const int bid  = blockIdx.x;
    const int grp  = bid / 13, off = bid % 13;   // 10 A + 3 B per 13
    const bool isA = off < 10;

    if (tid < NEXP) nw_s[tid] = nw[tid];

    if (isA) {
        // ================= Type A: tensor split-HMMA, 32 rows =================
        const int idxA = grp * 10 + off;
        const int base = idxA * 32;
        const int quad = lane & 3;
        const int r0   = lane >> 2;
        const int rowgrp = wid >> 1;
        const int eg     = wid & 1;

        const float* pA  = x + (size_t)(base + rowgrp * 16 + r0) * DDIM + quad * 2;
        const float* pA8 = pA + 8 * DDIM;
        const uint32_t* const Bp = Bfrag + (uint32_t)(eg * 4) * 64 + lane * 2;

        float c0[4][4], c1[4][4];
#pragma unroll
        for (int t = 0; t < 4; t++)
#pragma unroll
            for (int i = 0; i < 4; i++) { c0[t][i] = 0.f; c1[t][i] = 0.f; }

#define LDA(ch, a) do {                                                        \
    _Pragma("unroll")                                                          \
    for (int _s2 = 0; _s2 < 2; _s2++) {                                        \
        *(float2*)&(a)[_s2 * 8 + 0] = *(const float2*)(pA  + (ch) * 32 + _s2 * 16);     \
        *(float2*)&(a)[_s2 * 8 + 2] = *(const float2*)(pA8 + (ch) * 32 + _s2 * 16);     \
        *(float2*)&(a)[_s2 * 8 + 4] = *(const float2*)(pA  + (ch) * 32 + _s2 * 16 + 8); \
        *(float2*)&(a)[_s2 * 8 + 6] = *(const float2*)(pA8 + (ch) * 32 + _s2 * 16 + 8); \
    }                                                                          \
} while (0)
#define CHUNK_BODY(ch, aC, aN) do {                                            \
    if ((ch) + 1 < NCHUNK) LDA((ch) + 1, aN);                                  \
    _Pragma("unroll")                                                          \
    for (int _s = 0; _s < 2; _s++) {                                           \
        uint32_t ah[4], al[4];                                                 \
        _Pragma("unroll")                                                      \
        for (int _i = 0; _i < 4; _i++)                                         \
            split2(*(float2*)&(aC)[_s * 8 + _i * 2], ah[_i], al[_i]);          \
        const uint32_t* bp = Bp + ((uint32_t)(ch) * 2 + _s) * STEP_STRIDE;     \
        _Pragma("unroll")                                                      \
        for (int _t = 0; _t < 4; _t++) {                                       \
            uint2 bh = *(const uint2*)(bp + _t * 64);                          \
            uint2 bl = *(const uint2*)(bp + _t * 64 + 512);                    \
            float dd[4];                                                       \
            MMA_F16_NEW(dd, ah, bh.x, bh.y);                                   \
            MMA_F16_ACC(c1[_t], ah, bl.x, bl.y);                               \
            MMA_F16_ACC(c1[_t], al, bh.x, bh.y);                               \
            c0[_t][0] += dd[0]; c0[_t][1] += dd[1];                            \
            c0[_t][2] += dd[2]; c0[_t][3] += dd[3];                            \
        }                                                                      \
    }                                                                          \
} while (0)

        float aCur[16], aNxt[16];
        LDA(0, aCur);
#pragma unroll 1
        for (int cc = 0; cc < NCHUNK; cc += 2) {
            CHUNK_BODY(cc, aCur, aNxt);
            CHUNK_BODY(cc + 1, aNxt, aCur);
        }

        {
            int rA = rowgrp * 16 + r0;
#pragma unroll
            for (int t = 0; t < 4; t++) {
                int cb = (eg * 4 + t) * 8 + 2 * quad;
#pragma unroll
                for (int i = 0; i < 4; i++) {
                    float v = fmaf(c1[t][i], I11, c0[t][i]);
                    int rr = rA + (i >> 1) * 8;
                    SM[rr * 65 + cb + (i & 1)] = v;
                }
            }
        }
        __syncthreads();

        if (tid < 32)
            row_epilogue(SM, tid, base, lane, wsum[0], nw_s, noise, out_w, out_ids);
        __syncthreads();
        if (tid < NEXP)
            g_part[idxA * NEXP + tid] = wsum[0][tid];
    } else {
        // ================= Type B: exact fp32 FFMA GEMM, 64 rows =================
        const int idxB = grp * 3 + (off - 10);
        const int base = ROWS_A + idxB * 64;
        const int tx = tid & 15;     // 4 experts
        const int ty = tid >> 4;     // 8 rows
        float* const As = SM;
        float* const Bs = SM + 32 * 68;

        float acc[8][4];
#pragma unroll
        for (int r = 0; r < 8; r++)
#pragma unroll
            for (int e = 0; e < 4; e++) acc[r][e] = 0.f;

#pragma unroll 1
        for (int ch = 0; ch < NCHUNK; ch++) {
            __syncthreads();
#pragma unroll
            for (int i = 0; i < 4; i++) {
                int fid = tid + i * 128;
                int row = fid >> 3, q = fid & 7;
                float4 v = *(const float4*)(
                    x + (size_t)(base + row) * DDIM + ch * 32 + q * 4);
                As[(q * 4 + 0) * 68 + row] = v.x;
                As[(q * 4 + 1) * 68 + row] = v.y;
                As[(q * 4 + 2) * 68 + row] = v.z;
                As[(q * 4 + 3) * 68 + row] = v.w;
            }
#pragma unroll
            for (int i = 0; i < 4; i++) {
                int fid = tid + i * 128;
                int e = fid >> 3, q = fid & 7;
                float4 v = *(const float4*)(
                    w + (size_t)e * DDIM + ch * 32 + q * 4);
                Bs[(q * 4 + 0) * 68 + e] = v.x;
                Bs[(q * 4 + 1) * 68 + e] = v.y;
                Bs[(q * 4 + 2) * 68 + e] = v.z;
                Bs[(q * 4 + 3) * 68 + e] = v.w;
            }
            __syncthreads();
#pragma unroll
            for (int k = 0; k < 32; k++) {
                float4 a0 = *(const float4*)(As + k * 68 + ty * 8);
                float4 a1 = *(const float4*)(As + k * 68 + ty * 8 + 4);
                float4 b  = *(const float4*)(Bs + k * 68 + tx * 4);
                float av[8] = {a0.x, a0.y, a0.z, a0.w, a1.x, a1.y, a1.z, a1.w};
                float bv[4] = {b.x, b.y, b.z, b.w};
#pragma unroll
                for (int r = 0; r < 8; r++)
#pragma unroll
                    for (int e = 0; e < 4; e++)
                        acc[r][e] = fmaf(av[r], bv[e], acc[r][e]);
            }
        }
        __syncthreads();  // tiles dead; SM becomes canvas U[64][65]
#pragma unroll
        for (int r = 0; r < 8; r++)
#pragma unroll
            for (int e = 0; e < 4; e++)
                SM[(ty * 8 + r) * 65 + tx * 4 + e] = acc[r][e];
        __syncthreads();

        if (tid < 64)
            row_epilogue(SM, tid, base, lane, wsum[tid >> 5], nw_s, noise,
                         out_w, out_ids);
        __syncthreads();
        {
            int slot = NA + idxB * 2 + (tid >> 6);
            if (tid < 128)
                g_part[slot * NEXP + (tid & 63)] = wsum[tid >> 6][tid & 63];
        }
    }
}

__global__ void __launch_bounds__(1024) loss_kernel(
    int nSlots, int N, float* __restrict__ out_loss)
{
    __shared__ double red[1024];
    const int t = threadIdx.x;
    const int e = t & 63, g = t >> 6;
    double s = 0.0;
    for (int b = g; b < nSlots; b += 16) s += (double)g_part[b * NEXP + e];
    red[t] = s;
    __syncthreads();
    for (int off = 512; off >= 64; off >>= 1) {
        if (t < off) red[t] += red[t + off];
        __syncthreads();
    }
    if (t < 64) {
        double d = red[t] / (double)N - 1.0 / 64.0;
        red[t] = d * d;
    }
    __syncthreads();
    for (int off = 32; off >= 1; off >>= 1) {
        if (t < off) red[t] += red[t + off];
        __syncthreads();
    }
    if (t == 0) *out_loss = (float)(red[0] / 64.0 * 0.01);
}

extern "C" void kernel_launch(void* const* d_in, const int* in_sizes, int n_in,
                              void* d_out, int out_size)
{
    const float* x     = (const float*)d_in[0];  // [N, 1024]
    const float* w     = (const float*)d_in[1];  // [64, 1024]
    const float* nw    = (const float*)d_in[2];  // [64]
    const float* noise = (const float*)d_in[3];  // [N, 64]

    int N = in_sizes[3] / NEXP;                  // 32768
    int nB = (N - ROWS_A) / 64;                  // 192
    int grid = NA + nB;                          // 832 = 64 * 13

    float* out      = (float*)d_out;
    float* out_w    = out;
    float* out_ids  = out + (size_t)N * NEXP;
    float* out_loss = out + (size_t)N * NEXP + (size_t)N * KSEL;

    wsplit_kernel<<<128, 256>>>(w);
    gate_kernel<<<grid, 128>>>(x, w, nw, noise, out_w, out_ids);
    loss_kernel<<<1, 1024>>>(NA + nB * 2, N, out_loss);
}